// round 11
// baseline (speedup 1.0000x reference)
#include <cuda_runtime.h>

#define DM   64
#define H    2
#define DEG  8
#define L_MAX 100000
#define NODES_PB 32

// Scratch (static __device__ per allocation rules)
__device__ float g_kk[L_MAX * H * DM];   // [n][h][d]  = M_h @ x_n
__device__ float g_w [L_MAX * H];        // [n][h]     = (b_q^T W_k) . x_n
__device__ float g_MT[H * DM * DM];      // [h][dp][d] = sum_o Wq[o][d]*Wk[o][dp]
__device__ float g_a [H * DM];           // [h][dp]    = sum_o bq[o]*Wk[o][dp]

// ---- packed f32x2 helpers (forms mirror ptx_helpers.cuh PACK/UNPACK/FMA) ----
__device__ __forceinline__ unsigned long long pack2(float lo, float hi) {
    unsigned long long v;
    asm("mov.b64 %0, {%1, %2};" : "=l"(v)
        : "r"(__float_as_uint(lo)), "r"(__float_as_uint(hi)));
    return v;
}
__device__ __forceinline__ float2 unpack2(unsigned long long v) {
    unsigned int lo, hi;
    asm("mov.b64 {%0, %1}, %2;" : "=r"(lo), "=r"(hi) : "l"(v));
    return make_float2(__uint_as_float(lo), __uint_as_float(hi));
}
__device__ __forceinline__ unsigned long long ffma2(
    unsigned long long a, unsigned long long b, unsigned long long c) {
    unsigned long long d;
    asm("fma.rn.f32x2 %0, %1, %2, %3;" : "=l"(d) : "l"(a), "l"(b), "l"(c));
    return d;
}

// ---------------------------------------------------------------------------
// Kernel 0: fold W_q^T W_k and b_q^T W_k per head. Tiny (~1 MFLOP).
// ---------------------------------------------------------------------------
__global__ __launch_bounds__(256) void precompute_kernel(
    const float* __restrict__ W, const float* __restrict__ b)
{
    __shared__ float Wq[DM][DM];   // [o][d]
    __shared__ float Wk[DM][DM];   // [o][d]
    const int h = blockIdx.x;
    const int tid = threadIdx.x;

    const float* Wq_g = W + (h * 3 + 0) * DM * DM;
    const float* Wk_g = W + (h * 3 + 1) * DM * DM;
    for (int i = tid; i < DM * DM; i += 256) {
        Wq[i >> 6][i & 63] = Wq_g[i];
        Wk[i >> 6][i & 63] = Wk_g[i];
    }
    __syncthreads();

    for (int i = tid; i < DM * DM; i += 256) {
        const int dp = i >> 6, d = i & 63;
        float s = 0.f;
        #pragma unroll
        for (int o = 0; o < DM; o++) s += Wq[o][d] * Wk[o][dp];
        g_MT[h * DM * DM + i] = s;
    }
    if (tid < DM) {
        const float* bq = b + h * 3 * DM;
        float s = 0.f;
        #pragma unroll
        for (int o = 0; o < DM; o++) s += bq[o] * Wk[o][tid];
        g_a[h * DM + tid] = s;
    }
}

// ---------------------------------------------------------------------------
// Kernel 1: kk[n][j] = sum_dp x[n][dp] * B[dp][j],  j = h*64+d.
// 32-node x 128-col tile, 256 threads, 4x4 micro-tile computed as
// 2 node-pairs x 4 cols in packed f32x2: a-pairs come free from the
// xs LDS.128 (reinterpret as ulonglong2), only 4 bb broadcasts packed.
// Inner iter: 2 LDS.128 + 4 MOV.b64 (alu) + 8 FFMA2 (fma).
// ---------------------------------------------------------------------------
__global__ __launch_bounds__(256) void kk_gemm_kernel(
    const float* __restrict__ x, int L)
{
    __shared__ float xs[DM][NODES_PB];   // [dp][node]  8 KB
    __shared__ float Bs[DM][H * DM];     // [dp][j]    32 KB

    const int tid = threadIdx.x;
    const int n0  = blockIdx.x * NODES_PB;

    for (int i = tid; i < NODES_PB * DM; i += 256) {
        const int node = i >> 6, dp = i & 63;
        xs[dp][node] = (n0 + node < L) ? x[(n0 + node) * DM + dp] : 0.f;
    }
    for (int i = tid; i < DM * H * DM; i += 256) {
        const int dp = i >> 7, j = i & 127;
        Bs[dp][j] = g_MT[(j >> 6) * DM * DM + dp * DM + (j & 63)];
    }
    __syncthreads();

    const int tx = tid & 31;   // col group:  cols  tx*4 .. tx*4+3
    const int ty = tid >> 5;   // node group: nodes ty*4 .. ty*4+3

    // acc[p][c]: node-pair p (nodes ty*4+2p, ty*4+2p+1), column tx*4+c
    unsigned long long acc[2][4] = {{0ull,0ull,0ull,0ull},{0ull,0ull,0ull,0ull}};

    #pragma unroll
    for (int dp = 0; dp < DM; dp++) {
        const ulonglong2 av = *(const ulonglong2*)&xs[dp][ty * 4];  // (n0n1),(n2n3)
        const float4 bb = *(const float4*)&Bs[dp][tx * 4];
        const unsigned long long b0 = pack2(bb.x, bb.x);
        const unsigned long long b1 = pack2(bb.y, bb.y);
        const unsigned long long b2 = pack2(bb.z, bb.z);
        const unsigned long long b3 = pack2(bb.w, bb.w);
        acc[0][0] = ffma2(av.x, b0, acc[0][0]);
        acc[0][1] = ffma2(av.x, b1, acc[0][1]);
        acc[0][2] = ffma2(av.x, b2, acc[0][2]);
        acc[0][3] = ffma2(av.x, b3, acc[0][3]);
        acc[1][0] = ffma2(av.y, b0, acc[1][0]);
        acc[1][1] = ffma2(av.y, b1, acc[1][1]);
        acc[1][2] = ffma2(av.y, b2, acc[1][2]);
        acc[1][3] = ffma2(av.y, b3, acc[1][3]);
    }

    // epilogue: unpack into 4 per-node float4 rows and store
    const int col = tx * 4;
    #pragma unroll
    for (int p = 0; p < 2; p++) {
        const float2 v0 = unpack2(acc[p][0]);
        const float2 v1 = unpack2(acc[p][1]);
        const float2 v2 = unpack2(acc[p][2]);
        const float2 v3 = unpack2(acc[p][3]);
        int n = n0 + ty * 4 + 2 * p;
        if (n < L)
            *(float4*)&g_kk[n * (H*DM) + col] = make_float4(v0.x, v1.x, v2.x, v3.x);
        n += 1;
        if (n < L)
            *(float4*)&g_kk[n * (H*DM) + col] = make_float4(v0.y, v1.y, v2.y, v3.y);
    }

    // w[n][h] = a_h . x_n  (64 threads, trivial)
    if (tid < NODES_PB * H) {
        const int nl = tid & (NODES_PB - 1);
        const int h  = tid >> 5;
        float s = 0.f;
        #pragma unroll
        for (int dp = 0; dp < DM; dp++) s += xs[dp][nl] * g_a[h * DM + dp];
        if (n0 + nl < L) g_w[(n0 + nl) * H + h] = s;
    }
}

// ---------------------------------------------------------------------------
// Kernel 2: one thread per (node, head). s_j = 8*(x_r . kk_c + w_c),
// segment softmax over the node's 8 edges, head-mean via shfl with partner.
// Indices (2x int4) and all 8 g_w scalars loaded upfront; each dot uses
// 2 partial accumulators to halve the serial FFMA chain.
// ---------------------------------------------------------------------------
__global__ __launch_bounds__(128) void edge_softmax_kernel(
    const float* __restrict__ x, const int* __restrict__ cols,
    float* __restrict__ out, int L)
{
    const int g = blockIdx.x * 128 + threadIdx.x;
    if (g >= L * H) return;
    const int n = g >> 1;
    const int h = g & 1;

    // all 8 column indices in two vector loads
    const int4 c01 = ((const int4*)(cols + n * DEG))[0];
    const int4 c23 = ((const int4*)(cols + n * DEG))[1];
    int c[DEG] = {c01.x, c01.y, c01.z, c01.w, c23.x, c23.y, c23.z, c23.w};

    // bias terms upfront (independent loads, overlap with x reads)
    float wv[DEG];
    #pragma unroll
    for (int j = 0; j < DEG; j++) wv[j] = g_w[c[j] * H + h];

    float4 xr[16];
    const float4* xg = (const float4*)(x + n * DM);
    #pragma unroll
    for (int i = 0; i < 16; i++) xr[i] = xg[i];

    float s[DEG];
    #pragma unroll
    for (int j = 0; j < DEG; j++) {
        const float4* kg = (const float4*)(g_kk + c[j] * (H * DM) + h * DM);
        float d0 = 0.f, d1 = 0.f;
        #pragma unroll
        for (int i = 0; i < 16; i += 2) {
            const float4 ka = kg[i];
            const float4 kb = kg[i + 1];
            d0 += xr[i].x * ka.x + xr[i].y * ka.y + xr[i].z * ka.z + xr[i].w * ka.w;
            d1 += xr[i+1].x * kb.x + xr[i+1].y * kb.y + xr[i+1].z * kb.z + xr[i+1].w * kb.w;
        }
        s[j] = 8.0f * ((d0 + d1) + wv[j]);
    }

    float m = s[0];
    #pragma unroll
    for (int j = 1; j < DEG; j++) m = fmaxf(m, s[j]);

    float e[DEG];
    float z = 0.f;
    #pragma unroll
    for (int j = 0; j < DEG; j++) { e[j] = __expf(s[j] - m); z += e[j]; }
    const float inv = 1.0f / z;
    #pragma unroll
    for (int j = 0; j < DEG; j++) e[j] *= inv;

    // mean over heads: partner thread is lane^1 (same node, other head)
    #pragma unroll
    for (int j = 0; j < DEG; j++) {
        const float o = __shfl_xor_sync(0xffffffffu, e[j], 1);
        e[j] = 0.5f * (e[j] + o);
    }

    float4 r;
    if (h == 0) r = make_float4(e[0], e[1], e[2], e[3]);
    else        r = make_float4(e[4], e[5], e[6], e[7]);
    ((float4*)out)[n * 2 + h] = r;
}

// ---------------------------------------------------------------------------
extern "C" void kernel_launch(void* const* d_in, const int* in_sizes, int n_in,
                              void* d_out, int out_size)
{
    const float* x  = (const float*)d_in[0];   // [L, 64]
    const float* W  = (const float*)d_in[1];   // [384, 64]
    const float* b  = (const float*)d_in[2];   // [384]
    const int*   ei = (const int*)  d_in[3];   // [2, E]
    float* out = (float*)d_out;                // [E]

    const int L = in_sizes[0] / DM;
    const int E = in_sizes[3] / 2;
    const int* cols = ei + E;                  // rows are repeat(arange(L), 8)

    precompute_kernel<<<H, 256>>>(W, b);
    kk_gemm_kernel<<<(L + NODES_PB - 1) / NODES_PB, 256>>>(x, L);
    edge_softmax_kernel<<<(L * H + 127) / 128, 128>>>(x, cols, out, L);
    (void)n_in; (void)out_size; (void)E;
}

// round 12
// speedup vs baseline: 1.0587x; 1.0587x over previous
#include <cuda_runtime.h>

#define DM   64
#define H    2
#define DEG  8
#define L_MAX 100000
#define NODES_PB 32

// Scratch (static __device__ per allocation rules)
__device__ float g_kk[L_MAX * H * DM];   // [n][h][d]  = M_h @ x_n
__device__ float g_w [L_MAX * H];        // [n][h]     = (b_q^T W_k) . x_n
__device__ float g_MT[H * DM * DM];      // [h][dp][d] = sum_o Wq[o][d]*Wk[o][dp]
__device__ float g_a [H * DM];           // [h][dp]    = sum_o bq[o]*Wk[o][dp]

// ---- packed f32x2 helpers ----
__device__ __forceinline__ unsigned long long pack2(float lo, float hi) {
    unsigned long long v;
    asm("mov.b64 %0, {%1, %2};" : "=l"(v)
        : "r"(__float_as_uint(lo)), "r"(__float_as_uint(hi)));
    return v;
}
__device__ __forceinline__ float2 unpack2(unsigned long long v) {
    unsigned int lo, hi;
    asm("mov.b64 {%0, %1}, %2;" : "=r"(lo), "=r"(hi) : "l"(v));
    return make_float2(__uint_as_float(lo), __uint_as_float(hi));
}
__device__ __forceinline__ unsigned long long ffma2(
    unsigned long long a, unsigned long long b, unsigned long long c) {
    unsigned long long d;
    asm("fma.rn.f32x2 %0, %1, %2, %3;" : "=l"(d) : "l"(a), "l"(b), "l"(c));
    return d;
}

// ---------------------------------------------------------------------------
// Kernel 0 (rewritten): one thread per output element of M = Wq^T Wk.
// 8192 dot-products of length 64, 4-way split chains, 33 blocks -> wave
// parallel instead of the old 2-block latency-bound version (18.3us -> ~4us).
// Block 32 handles the tiny g_a vector.
// ---------------------------------------------------------------------------
__global__ __launch_bounds__(256) void precompute_kernel(
    const float* __restrict__ W, const float* __restrict__ b)
{
    const int bid = blockIdx.x;
    const int tid = threadIdx.x;

    if (bid < 32) {
        // M outputs: gid in [0, H*64*64)
        const int gid = bid * 256 + tid;
        const int h  = gid >> 12;          // /4096
        const int i  = gid & 4095;
        const int dp = i >> 6;
        const int d  = i & 63;
        const float* Wq_g = W + (h * 3 + 0) * DM * DM;
        const float* Wk_g = W + (h * 3 + 1) * DM * DM;
        float s0 = 0.f, s1 = 0.f, s2 = 0.f, s3 = 0.f;
        #pragma unroll
        for (int o = 0; o < DM; o += 4) {
            s0 += Wq_g[(o + 0) * DM + d] * Wk_g[(o + 0) * DM + dp];
            s1 += Wq_g[(o + 1) * DM + d] * Wk_g[(o + 1) * DM + dp];
            s2 += Wq_g[(o + 2) * DM + d] * Wk_g[(o + 2) * DM + dp];
            s3 += Wq_g[(o + 3) * DM + d] * Wk_g[(o + 3) * DM + dp];
        }
        // g_MT[h][dp][d]
        g_MT[h * DM * DM + dp * DM + d] = (s0 + s1) + (s2 + s3);
    } else {
        // g_a[h][dp] = sum_o bq[o] * Wk[o][dp]
        if (tid < H * DM) {
            const int h  = tid >> 6;
            const int dp = tid & 63;
            const float* Wk_g = W + (h * 3 + 1) * DM * DM;
            const float* bq   = b + h * 3 * DM;
            float s0 = 0.f, s1 = 0.f;
            #pragma unroll
            for (int o = 0; o < DM; o += 2) {
                s0 += bq[o]     * Wk_g[o * DM + dp];
                s1 += bq[o + 1] * Wk_g[(o + 1) * DM + dp];
            }
            g_a[h * DM + dp] = s0 + s1;
        }
    }
}

// ---------------------------------------------------------------------------
// Kernel 1: kk[n][j] = sum_dp x[n][dp] * B[dp][j],  j = h*64+d.
// 32-node x 128-col tile, 256 threads, packed f32x2 micro-kernel.
// ---------------------------------------------------------------------------
__global__ __launch_bounds__(256) void kk_gemm_kernel(
    const float* __restrict__ x, int L)
{
    __shared__ float xs[DM][NODES_PB];   // [dp][node]  8 KB
    __shared__ float Bs[DM][H * DM];     // [dp][j]    32 KB

    const int tid = threadIdx.x;
    const int n0  = blockIdx.x * NODES_PB;

    for (int i = tid; i < NODES_PB * DM; i += 256) {
        const int node = i >> 6, dp = i & 63;
        xs[dp][node] = (n0 + node < L) ? x[(n0 + node) * DM + dp] : 0.f;
    }
    for (int i = tid; i < DM * H * DM; i += 256) {
        const int dp = i >> 7, j = i & 127;
        Bs[dp][j] = g_MT[(j >> 6) * DM * DM + dp * DM + (j & 63)];
    }
    __syncthreads();

    const int tx = tid & 31;
    const int ty = tid >> 5;

    unsigned long long acc[2][4] = {{0ull,0ull,0ull,0ull},{0ull,0ull,0ull,0ull}};

    #pragma unroll
    for (int dp = 0; dp < DM; dp++) {
        const ulonglong2 av = *(const ulonglong2*)&xs[dp][ty * 4];
        const float4 bb = *(const float4*)&Bs[dp][tx * 4];
        const unsigned long long b0 = pack2(bb.x, bb.x);
        const unsigned long long b1 = pack2(bb.y, bb.y);
        const unsigned long long b2 = pack2(bb.z, bb.z);
        const unsigned long long b3 = pack2(bb.w, bb.w);
        acc[0][0] = ffma2(av.x, b0, acc[0][0]);
        acc[0][1] = ffma2(av.x, b1, acc[0][1]);
        acc[0][2] = ffma2(av.x, b2, acc[0][2]);
        acc[0][3] = ffma2(av.x, b3, acc[0][3]);
        acc[1][0] = ffma2(av.y, b0, acc[1][0]);
        acc[1][1] = ffma2(av.y, b1, acc[1][1]);
        acc[1][2] = ffma2(av.y, b2, acc[1][2]);
        acc[1][3] = ffma2(av.y, b3, acc[1][3]);
    }

    const int col = tx * 4;
    #pragma unroll
    for (int p = 0; p < 2; p++) {
        const float2 v0 = unpack2(acc[p][0]);
        const float2 v1 = unpack2(acc[p][1]);
        const float2 v2 = unpack2(acc[p][2]);
        const float2 v3 = unpack2(acc[p][3]);
        int n = n0 + ty * 4 + 2 * p;
        if (n < L)
            *(float4*)&g_kk[n * (H*DM) + col] = make_float4(v0.x, v1.x, v2.x, v3.x);
        n += 1;
        if (n < L)
            *(float4*)&g_kk[n * (H*DM) + col] = make_float4(v0.y, v1.y, v2.y, v3.y);
    }

    if (tid < NODES_PB * H) {
        const int nl = tid & (NODES_PB - 1);
        const int h  = tid >> 5;
        float s = 0.f;
        #pragma unroll
        for (int dp = 0; dp < DM; dp++) s += xs[dp][nl] * g_a[h * DM + dp];
        if (n0 + nl < L) g_w[(n0 + nl) * H + h] = s;
    }
}

// ---------------------------------------------------------------------------
// Kernel 2 (restructured): one thread per (node, head). Chunk-streamed dots:
// loop over 16 x-chunks; per chunk load 1 x float4 + 8 kk float4s (9
// independent LDGs -> steady MLP) and FMA into 8 per-edge accumulators.
// Cuts register pressure from ~110 (whole-x-resident) to ~60.
// ---------------------------------------------------------------------------
__global__ __launch_bounds__(128) void edge_softmax_kernel(
    const float* __restrict__ x, const int* __restrict__ cols,
    float* __restrict__ out, int L)
{
    const int g = blockIdx.x * 128 + threadIdx.x;
    if (g >= L * H) return;
    const int n = g >> 1;
    const int h = g & 1;

    const int4 c01 = ((const int4*)(cols + n * DEG))[0];
    const int4 c23 = ((const int4*)(cols + n * DEG))[1];
    const int c[DEG] = {c01.x, c01.y, c01.z, c01.w, c23.x, c23.y, c23.z, c23.w};

    float wv[DEG];
    #pragma unroll
    for (int j = 0; j < DEG; j++) wv[j] = g_w[c[j] * H + h];

    const float4* kb[DEG];
    #pragma unroll
    for (int j = 0; j < DEG; j++)
        kb[j] = (const float4*)(g_kk + c[j] * (H * DM) + h * DM);

    const float4* xg = (const float4*)(x + n * DM);

    float acc[DEG] = {0.f,0.f,0.f,0.f,0.f,0.f,0.f,0.f};
    #pragma unroll
    for (int i = 0; i < 16; i++) {
        const float4 xv = xg[i];
        #pragma unroll
        for (int j = 0; j < DEG; j++) {
            const float4 k4 = kb[j][i];
            acc[j] += xv.x * k4.x + xv.y * k4.y + xv.z * k4.z + xv.w * k4.w;
        }
    }

    float s[DEG];
    #pragma unroll
    for (int j = 0; j < DEG; j++) s[j] = 8.0f * (acc[j] + wv[j]);

    float m = s[0];
    #pragma unroll
    for (int j = 1; j < DEG; j++) m = fmaxf(m, s[j]);

    float e[DEG];
    float z = 0.f;
    #pragma unroll
    for (int j = 0; j < DEG; j++) { e[j] = __expf(s[j] - m); z += e[j]; }
    const float inv = 1.0f / z;
    #pragma unroll
    for (int j = 0; j < DEG; j++) e[j] *= inv;

    #pragma unroll
    for (int j = 0; j < DEG; j++) {
        const float o = __shfl_xor_sync(0xffffffffu, e[j], 1);
        e[j] = 0.5f * (e[j] + o);
    }

    float4 r;
    if (h == 0) r = make_float4(e[0], e[1], e[2], e[3]);
    else        r = make_float4(e[4], e[5], e[6], e[7]);
    ((float4*)out)[n * 2 + h] = r;
}

// ---------------------------------------------------------------------------
extern "C" void kernel_launch(void* const* d_in, const int* in_sizes, int n_in,
                              void* d_out, int out_size)
{
    const float* x  = (const float*)d_in[0];   // [L, 64]
    const float* W  = (const float*)d_in[1];   // [384, 64]
    const float* b  = (const float*)d_in[2];   // [384]
    const int*   ei = (const int*)  d_in[3];   // [2, E]
    float* out = (float*)d_out;                // [E]

    const int L = in_sizes[0] / DM;
    const int E = in_sizes[3] / 2;
    const int* cols = ei + E;                  // rows are repeat(arange(L), 8)

    precompute_kernel<<<33, 256>>>(W, b);
    kk_gemm_kernel<<<(L + NODES_PB - 1) / NODES_PB, 256>>>(x, L);
    edge_softmax_kernel<<<(L * H + 127) / 128, 128>>>(x, cols, out, L);
    (void)n_in; (void)out_size; (void)E;
}